// round 4
// baseline (speedup 1.0000x reference)
#include <cuda_runtime.h>
#include <cuda_bf16.h>
#include <cstdint>

#define MDIM 8192
#define KDIM 4096
#define NDIM 4096

#define TILE_M 128
#define TILE_N 256
#define TILE_K 64
#define NK_ITERS (KDIM / TILE_K)   // 64
#define NSTAGES 4
#define THREADS 256

// bf16 scratch (device globals = allowed scratch)
__device__ __nv_bfloat16 g_xq[(size_t)MDIM * KDIM];
__device__ __nv_bfloat16 g_wq[(size_t)NDIM * KDIM];

// ---------------- helpers ----------------
__device__ __forceinline__ uint32_t smem_u32(const void* p) {
    uint32_t a;
    asm("{ .reg .u64 t; cvta.to.shared.u64 t, %1; cvt.u32.u64 %0, t; }" : "=r"(a) : "l"(p));
    return a;
}
__device__ __forceinline__ void cp_async16(uint32_t s, const void* g) {
    asm volatile("cp.async.cg.shared.global [%0], [%1], 16;" :: "r"(s), "l"(g));
}
__device__ __forceinline__ void cp_commit() { asm volatile("cp.async.commit_group;"); }
template <int N> __device__ __forceinline__ void cp_wait() {
    asm volatile("cp.async.wait_group %0;" :: "n"(N));
}
__device__ __forceinline__ void ldm_x4(uint32_t* r, uint32_t addr) {
    asm volatile("ldmatrix.sync.aligned.m8n8.x4.shared.b16 {%0,%1,%2,%3}, [%4];"
                 : "=r"(r[0]), "=r"(r[1]), "=r"(r[2]), "=r"(r[3]) : "r"(addr));
}
__device__ __forceinline__ void mma_bf16(float* d, const uint32_t* a, const uint32_t* b) {
    asm volatile(
        "mma.sync.aligned.m16n8k16.row.col.f32.bf16.bf16.f32 "
        "{%0,%1,%2,%3}, {%4,%5,%6,%7}, {%8,%9}, {%0,%1,%2,%3};"
        : "+f"(d[0]), "+f"(d[1]), "+f"(d[2]), "+f"(d[3])
        : "r"(a[0]), "r"(a[1]), "r"(a[2]), "r"(a[3]), "r"(b[0]), "r"(b[1]));
}
__device__ __forceinline__ uint32_t pack_bf16(float a, float b) {
    __nv_bfloat162 t = __floats2bfloat162_rn(a, b);
    return *reinterpret_cast<uint32_t*>(&t);
}

// ---------------- quantize x -> bf16(int) ----------------
__global__ void __launch_bounds__(256) quant_kernel(const float* __restrict__ x,
                                                    const float* __restrict__ is_p,
                                                    const int* __restrict__ izp_p) {
    int idx = (blockIdx.x * 256 + threadIdx.x) * 4;
    float inv = 1.0f / is_p[0];
    float zp = (float)izp_p[0];
    float4 v = *(const float4*)(x + idx);
    float q0 = fminf(fmaxf(rintf(v.x * inv) + zp, -128.f), 127.f) - zp;
    float q1 = fminf(fmaxf(rintf(v.y * inv) + zp, -128.f), 127.f) - zp;
    float q2 = fminf(fmaxf(rintf(v.z * inv) + zp, -128.f), 127.f) - zp;
    float q3 = fminf(fmaxf(rintf(v.w * inv) + zp, -128.f), 127.f) - zp;
    uint2 o;
    o.x = pack_bf16(q0, q1);
    o.y = pack_bf16(q2, q3);
    *reinterpret_cast<uint2*>(g_xq + idx) = o;
}

// ---------------- weight int32 -> bf16 ----------------
__global__ void __launch_bounds__(256) wconv_kernel(const int* __restrict__ w,
                                                    const int* __restrict__ wzp) {
    int n = blockIdx.y;
    int k = (blockIdx.x * 256 + threadIdx.x) * 4;
    int zp = wzp[n];
    size_t base = (size_t)n * KDIM + k;
    int4 v = *(const int4*)(w + base);
    uint2 o;
    o.x = pack_bf16((float)(v.x - zp), (float)(v.y - zp));
    o.y = pack_bf16((float)(v.z - zp), (float)(v.w - zp));
    *reinterpret_cast<uint2*>(g_wq + base) = o;
}

// ---------------- HMMA bf16 GEMM: 128x256 CTA, 8 warps, warp 64x64 ----------------
// smem: alpha[256] f32 @0, beta[256] f32 @1024, stages @2048
// stage: A 128 rows x 144B (18432) + B 256 rows x 144B (36864) = 55296
#define STRIDE_ROW 144
#define S_AB 2048
#define A_BYTES 18432
#define STAGE_BYTES 55296
#define SMEM_BYTES (S_AB + NSTAGES * STAGE_BYTES)   // 223232

__device__ __forceinline__ void load_stage(uint32_t sbase, int stage,
                                           const __nv_bfloat16* gA,
                                           const __nv_bfloat16* gB,
                                           int k0, int tid) {
    uint32_t sA = sbase + S_AB + stage * STAGE_BYTES;
    uint32_t sB = sA + A_BYTES;
#pragma unroll
    for (int i = 0; i < 4; i++) {   // A: 128 rows x 8 chunks(16B) = 1024
        int idx = tid + THREADS * i;
        int row = idx >> 3, ch = idx & 7;
        cp_async16(sA + row * STRIDE_ROW + ch * 16,
                   gA + (size_t)row * KDIM + k0 + ch * 8);
    }
#pragma unroll
    for (int i = 0; i < 8; i++) {   // B: 256 rows x 8 chunks = 2048
        int idx = tid + THREADS * i;
        int row = idx >> 3, ch = idx & 7;
        cp_async16(sB + row * STRIDE_ROW + ch * 16,
                   gB + (size_t)row * KDIM + k0 + ch * 8);
    }
}

__global__ void __launch_bounds__(THREADS, 1)
gemm_kernel(const float* __restrict__ wscale, const float* __restrict__ in_scale,
            const int* __restrict__ bias_int, const float* __restrict__ bias_scale,
            float* __restrict__ out) {
    extern __shared__ __align__(1024) char smem[];
    const uint32_t sbase = smem_u32(smem);
    const int tid = threadIdx.x;
    const int lane = tid & 31;
    const int wid = tid >> 5;
    const int warpM = wid >> 2;       // 2 -> 64 rows each
    const int warpN = wid & 3;        // 4 -> 64 cols each

    // raster: groups of 8 m-tiles x 16 n-tiles (keeps B L2-resident)
    const int tiles_n = NDIM / TILE_N;              // 16
    const int per_group = 8 * tiles_n;              // 128
    int g = blockIdx.x / per_group;
    int r0 = blockIdx.x % per_group;
    int mt = g * 8 + (r0 & 7);
    int nt = r0 >> 3;
    const int m0 = mt * TILE_M;
    const int n0 = nt * TILE_N;

    float* alpha_s = (float*)smem;
    float* beta_s = (float*)(smem + 1024);
    if (tid < 256) {
        int n = n0 + tid;
        alpha_s[tid] = in_scale[0] * wscale[n];
        beta_s[tid] = (float)bias_int[n] * bias_scale[n];
    }

    const __nv_bfloat16* gA = g_xq + (size_t)m0 * KDIM;
    const __nv_bfloat16* gB = g_wq + (size_t)n0 * KDIM;

    // prologue: stages 0..2 in flight
    load_stage(sbase, 0, gA, gB, 0, tid); cp_commit();
    load_stage(sbase, 1, gA, gB, TILE_K, tid); cp_commit();
    load_stage(sbase, 2, gA, gB, 2 * TILE_K, tid); cp_commit();

    float acc[4][8][4];
#pragma unroll
    for (int i = 0; i < 4; i++)
#pragma unroll
        for (int j = 0; j < 8; j++)
#pragma unroll
            for (int q = 0; q < 4; q++) acc[i][j][q] = 0.0f;

    // ldmatrix lane-address components
    const int a_row = lane & 15;                        // m rows 0-15
    const int a_kh = (lane >> 4) & 1;                   // +16B k-half
    const int b_noff = (lane & 7) + ((lane & 16) >> 1); // n rows 0-15
    const int b_kh = (lane >> 3) & 1;                   // +16B k-half

#pragma unroll 1
    for (int it = 0; it < NK_ITERS; it++) {
        cp_wait<NSTAGES - 2>();
        __syncthreads();

        if (it + 3 < NK_ITERS) {
            load_stage(sbase, (it + 3) & (NSTAGES - 1), gA, gB, (it + 3) * TILE_K, tid);
            cp_commit();
        } else {
            cp_commit();
        }

        uint32_t sA = sbase + S_AB + (it & (NSTAGES - 1)) * STAGE_BYTES;
        uint32_t sB = sA + A_BYTES;
        uint32_t aBase = sA + (warpM * 64 + a_row) * STRIDE_ROW + a_kh * 16;
        uint32_t bBase = sB + (warpN * 64 + b_noff) * STRIDE_ROW + b_kh * 16;

#pragma unroll
        for (int ks = 0; ks < 4; ks++) {   // four k=16 steps
            uint32_t a[4][4], b[4][4];
#pragma unroll
            for (int mi = 0; mi < 4; mi++)
                ldm_x4(a[mi], aBase + mi * (16 * STRIDE_ROW) + ks * 32);
#pragma unroll
            for (int np = 0; np < 4; np++)
                ldm_x4(b[np], bBase + np * (16 * STRIDE_ROW) + ks * 32);
#pragma unroll
            for (int mi = 0; mi < 4; mi++)
#pragma unroll
                for (int ni = 0; ni < 8; ni++)
                    mma_bf16(acc[mi][ni], a[mi], &b[ni >> 1][(ni & 1) * 2]);
        }
    }

    // epilogue: dequant + bias, direct stores
    const int gid = lane >> 2, tig = lane & 3;
#pragma unroll
    for (int mi = 0; mi < 4; mi++) {
#pragma unroll
        for (int ni = 0; ni < 8; ni++) {
            int nloc = warpN * 64 + ni * 8 + tig * 2;
            float al0 = alpha_s[nloc], al1 = alpha_s[nloc + 1];
            float be0 = beta_s[nloc], be1 = beta_s[nloc + 1];
            size_t r = (size_t)m0 + warpM * 64 + mi * 16 + gid;
            float2 v0 = {acc[mi][ni][0] * al0 + be0, acc[mi][ni][1] * al1 + be1};
            float2 v1 = {acc[mi][ni][2] * al0 + be0, acc[mi][ni][3] * al1 + be1};
            *reinterpret_cast<float2*>(out + r * NDIM + n0 + nloc) = v0;
            *reinterpret_cast<float2*>(out + (r + 8) * NDIM + n0 + nloc) = v1;
        }
    }
}

// ---------------- launch ----------------
extern "C" void kernel_launch(void* const* d_in, const int* in_sizes, int n_in,
                              void* d_out, int out_size) {
    const float* x = (const float*)d_in[0];
    const int* w = (const int*)d_in[1];
    const float* wsc = (const float*)d_in[2];
    const int* wzp = (const int*)d_in[3];
    const float* isc = (const float*)d_in[4];
    const int* izp = (const int*)d_in[5];
    const int* bi = (const int*)d_in[6];
    const float* bsc = (const float*)d_in[7];
    float* out = (float*)d_out;

    cudaFuncSetAttribute(gemm_kernel, cudaFuncAttributeMaxDynamicSharedMemorySize,
                         SMEM_BYTES);

    quant_kernel<<<(MDIM * KDIM) / 1024, 256>>>(x, isc, izp);
    wconv_kernel<<<dim3(KDIM / 1024, NDIM), 256>>>(w, wzp);
    gemm_kernel<<<(MDIM / TILE_M) * (NDIM / TILE_N), THREADS, SMEM_BYTES>>>(
        wsc, isc, bi, bsc, out);
}

// round 5
// speedup vs baseline: 1.1844x; 1.1844x over previous
#include <cuda_runtime.h>
#include <cuda_bf16.h>
#include <cstdint>

#define MDIM 8192
#define KDIM 4096
#define NDIM 4096

#define TILE_M 128
#define TILE_N 256
#define TILE_K 64
#define NK_ITERS (KDIM / TILE_K)   // 64
#define NSTAGES 4
#define THREADS 512

// Tile-major pre-swizzled scratch:
// g_xq: [mt(64)][ks(64)] tiles of 128x64 bf16 (16384 B each), rows 128B, XOR-swizzled
// g_wq: [nt(16)][ks(64)] tiles of 256x64 bf16 (32768 B each)
__device__ __nv_bfloat16 g_xq[(size_t)MDIM * KDIM];
__device__ __nv_bfloat16 g_wq[(size_t)NDIM * KDIM];

#define A_TILE_BYTES 16384
#define B_TILE_BYTES 32768

// ---------------- helpers ----------------
__device__ __forceinline__ uint32_t smem_u32(const void* p) {
    uint32_t a;
    asm("{ .reg .u64 t; cvta.to.shared.u64 t, %1; cvt.u32.u64 %0, t; }" : "=r"(a) : "l"(p));
    return a;
}
__device__ __forceinline__ void ldm_x4(uint32_t* r, uint32_t addr) {
    asm volatile("ldmatrix.sync.aligned.m8n8.x4.shared.b16 {%0,%1,%2,%3}, [%4];"
                 : "=r"(r[0]), "=r"(r[1]), "=r"(r[2]), "=r"(r[3]) : "r"(addr));
}
__device__ __forceinline__ void mma_bf16(float* d, const uint32_t* a, const uint32_t* b) {
    asm volatile(
        "mma.sync.aligned.m16n8k16.row.col.f32.bf16.bf16.f32 "
        "{%0,%1,%2,%3}, {%4,%5,%6,%7}, {%8,%9}, {%0,%1,%2,%3};"
        : "+f"(d[0]), "+f"(d[1]), "+f"(d[2]), "+f"(d[3])
        : "r"(a[0]), "r"(a[1]), "r"(a[2]), "r"(a[3]), "r"(b[0]), "r"(b[1]));
}
__device__ __forceinline__ uint32_t pack_bf16(float a, float b) {
    __nv_bfloat162 t = __floats2bfloat162_rn(a, b);
    return *reinterpret_cast<uint32_t*>(&t);
}
__device__ __forceinline__ void bulk_ld(uint32_t dst, const void* src, uint32_t bytes,
                                        uint32_t mbar) {
    asm volatile(
        "cp.async.bulk.shared::cta.global.mbarrier::complete_tx::bytes [%0], [%1], %2, [%3];"
        :: "r"(dst), "l"(src), "r"(bytes), "r"(mbar) : "memory");
}
#define MBAR_INIT(addr, cnt) \
    asm volatile("mbarrier.init.shared.b64 [%0], %1;" :: "r"(addr), "r"(cnt) : "memory")
#define MBAR_EXPECT_TX(addr, bytes) \
    asm volatile("mbarrier.arrive.expect_tx.shared.b64 _, [%0], %1;" \
                 :: "r"(addr), "r"(bytes) : "memory")
__device__ __forceinline__ void mbar_wait(uint32_t mbar, uint32_t parity) {
    asm volatile(
        "{\n\t"
        ".reg .pred P;\n\t"
        "WAIT_%=:\n\t"
        "mbarrier.try_wait.parity.acquire.cta.shared::cta.b64 P, [%0], %1, 0x989680;\n\t"
        "@P bra DONE_%=;\n\t"
        "bra WAIT_%=;\n\t"
        "DONE_%=:\n\t"
        "}" :: "r"(mbar), "r"(parity) : "memory");
}

// ---------------- quantize x -> bf16(int), tile-major swizzled ----------------
// thread handles 8 consecutive floats (one 16B output unit)
__global__ void __launch_bounds__(256) quant_kernel(const float* __restrict__ x,
                                                    const float* __restrict__ is_p,
                                                    const int* __restrict__ izp_p) {
    size_t base = ((size_t)blockIdx.x * 256 + threadIdx.x) * 8;
    float inv = 1.0f / is_p[0];
    float zp = (float)izp_p[0];
    float4 v0 = *(const float4*)(x + base);
    float4 v1 = *(const float4*)(x + base + 4);
    float q[8];
    q[0] = v0.x; q[1] = v0.y; q[2] = v0.z; q[3] = v0.w;
    q[4] = v1.x; q[5] = v1.y; q[6] = v1.z; q[7] = v1.w;
#pragma unroll
    for (int i = 0; i < 8; i++)
        q[i] = fminf(fmaxf(rintf(q[i] * inv) + zp, -128.f), 127.f) - zp;
    uint4 o;
    o.x = pack_bf16(q[0], q[1]);
    o.y = pack_bf16(q[2], q[3]);
    o.z = pack_bf16(q[4], q[5]);
    o.w = pack_bf16(q[6], q[7]);
    int m = (int)(base >> 12);           // K=4096
    int k = (int)(base & 4095);
    int mt = m >> 7, row = m & 127;
    int ks = k >> 6, u = (k & 63) >> 3;
    size_t dst = (size_t)(mt * 64 + ks) * A_TILE_BYTES +
                 row * 128 + ((u ^ (row & 7)) << 4);
    *reinterpret_cast<uint4*>(reinterpret_cast<char*>(g_xq) + dst) = o;
}

// ---------------- weight int32 -> bf16, tile-major swizzled ----------------
__global__ void __launch_bounds__(256) wconv_kernel(const int* __restrict__ w,
                                                    const int* __restrict__ wzp) {
    size_t base = ((size_t)blockIdx.x * 256 + threadIdx.x) * 8;
    int n = (int)(base >> 12);
    int k = (int)(base & 4095);
    int zp = wzp[n];
    int4 a = *(const int4*)(w + base);
    int4 b = *(const int4*)(w + base + 4);
    uint4 o;
    o.x = pack_bf16((float)(a.x - zp), (float)(a.y - zp));
    o.y = pack_bf16((float)(a.z - zp), (float)(a.w - zp));
    o.z = pack_bf16((float)(b.x - zp), (float)(b.y - zp));
    o.w = pack_bf16((float)(b.z - zp), (float)(b.w - zp));
    int nt = n >> 8, row = n & 255;
    int ks = k >> 6, u = (k & 63) >> 3;
    size_t dst = (size_t)(nt * 64 + ks) * B_TILE_BYTES +
                 row * 128 + ((u ^ (row & 7)) << 4);
    *reinterpret_cast<uint4*>(reinterpret_cast<char*>(g_wq) + dst) = o;
}

// ---------------- HMMA bf16 GEMM with bulk-copy pipeline ----------------
// smem: [0,32) mbars(4x8B), [128,1152) alpha, [1152,2176) beta, stages @4096
#define S_STAGE (A_TILE_BYTES + B_TILE_BYTES)   // 49152
#define S_BUF 4096
#define SMEM_BYTES (S_BUF + NSTAGES * S_STAGE)  // 200704

__global__ void __launch_bounds__(THREADS, 1)
gemm_kernel(const float* __restrict__ wscale, const float* __restrict__ in_scale,
            const int* __restrict__ bias_int, const float* __restrict__ bias_scale,
            float* __restrict__ out) {
    extern __shared__ __align__(1024) char smem[];
    const uint32_t sbase = smem_u32(smem);
    const int tid = threadIdx.x;
    const int lane = tid & 31;
    const int wid = tid >> 5;
    const int warpM = wid & 3;        // 4 -> 32 rows each
    const int warpN = wid >> 2;       // 4 -> 64 cols each

    // raster: groups of 8 m-tiles x 16 n-tiles (keeps B L2-resident)
    const int tiles_n = NDIM / TILE_N;              // 16
    const int per_group = 8 * tiles_n;              // 128
    int g = blockIdx.x / per_group;
    int r0 = blockIdx.x % per_group;
    int mt = g * 8 + (r0 & 7);
    int nt = r0 >> 3;
    const int m0 = mt * TILE_M;
    const int n0 = nt * TILE_N;

    float* alpha_s = (float*)(smem + 128);
    float* beta_s = (float*)(smem + 1152);
    if (tid < 256) {
        int n = n0 + tid;
        alpha_s[tid] = in_scale[0] * wscale[n];
        beta_s[tid] = (float)bias_int[n] * bias_scale[n];
    }

    const char* gA = reinterpret_cast<const char*>(g_xq) + (size_t)mt * 64 * A_TILE_BYTES;
    const char* gB = reinterpret_cast<const char*>(g_wq) + (size_t)nt * 64 * B_TILE_BYTES;

    if (tid == 0) {
#pragma unroll
        for (int s = 0; s < NSTAGES; s++) MBAR_INIT(sbase + s * 8, 1);
    }
    __syncthreads();

    // prologue: stages 0..2 in flight
    if (tid == 0) {
#pragma unroll
        for (int s = 0; s < 3; s++) {
            uint32_t mb = sbase + s * 8;
            uint32_t dst = sbase + S_BUF + s * S_STAGE;
            MBAR_EXPECT_TX(mb, S_STAGE);
            bulk_ld(dst, gA + (size_t)s * A_TILE_BYTES, A_TILE_BYTES, mb);
            bulk_ld(dst + A_TILE_BYTES, gB + (size_t)s * B_TILE_BYTES, B_TILE_BYTES, mb);
        }
    }

    float acc[2][8][4];
#pragma unroll
    for (int i = 0; i < 2; i++)
#pragma unroll
        for (int j = 0; j < 8; j++)
#pragma unroll
            for (int q = 0; q < 4; q++) acc[i][j][q] = 0.0f;

    // ldmatrix lane-address components (swizzled rows of 128B)
    const int a_row = lane & 15;
    const int a_kh = (lane >> 4) & 1;
    const int b_noff = (lane & 7) + ((lane & 16) >> 1);
    const int b_kh = (lane >> 3) & 1;

    // per-warp row bases and swizzle parities
    int rA[2], rB[4];
#pragma unroll
    for (int mi = 0; mi < 2; mi++) rA[mi] = warpM * 32 + mi * 16 + a_row;
#pragma unroll
    for (int np = 0; np < 4; np++) rB[np] = warpN * 64 + np * 16 + b_noff;

#pragma unroll 1
    for (int it = 0; it < NK_ITERS; it++) {
        // issue prefetch for stage it+3 into ring slot (it+3)&3 = (it-1)&3.
        // Safe: __syncthreads() at end of iter it-1 released that slot.
        if (tid == 0 && it + 3 < NK_ITERS) {
            int s = (it + 3) & (NSTAGES - 1);
            uint32_t mb = sbase + s * 8;
            uint32_t dst = sbase + S_BUF + s * S_STAGE;
            MBAR_EXPECT_TX(mb, S_STAGE);
            bulk_ld(dst, gA + (size_t)(it + 3) * A_TILE_BYTES, A_TILE_BYTES, mb);
            bulk_ld(dst + A_TILE_BYTES, gB + (size_t)(it + 3) * B_TILE_BYTES, B_TILE_BYTES, mb);
        }

        int slot = it & (NSTAGES - 1);
        mbar_wait(sbase + slot * 8, (it >> 2) & 1);

        uint32_t sA = sbase + S_BUF + slot * S_STAGE;
        uint32_t sB = sA + A_TILE_BYTES;

#pragma unroll
        for (int ks = 0; ks < 4; ks++) {   // four k=16 steps
            uint32_t a[2][4], b[4][4];
            int uA = ks * 2 + a_kh;
            int uB = ks * 2 + b_kh;
#pragma unroll
            for (int mi = 0; mi < 2; mi++)
                ldm_x4(a[mi], sA + rA[mi] * 128 + ((uA ^ (rA[mi] & 7)) << 4));
#pragma unroll
            for (int np = 0; np < 4; np++)
                ldm_x4(b[np], sB + rB[np] * 128 + ((uB ^ (rB[np] & 7)) << 4));
#pragma unroll
            for (int mi = 0; mi < 2; mi++)
#pragma unroll
                for (int ni = 0; ni < 8; ni++)
                    mma_bf16(acc[mi][ni], a[mi], &b[ni >> 1][(ni & 1) * 2]);
        }
        __syncthreads();   // release this slot for overwrite at iter it+1
    }

    // epilogue: dequant + bias, direct stores
    const int gid = lane >> 2, tig = lane & 3;
#pragma unroll
    for (int mi = 0; mi < 2; mi++) {
#pragma unroll
        for (int ni = 0; ni < 8; ni++) {
            int nloc = warpN * 64 + ni * 8 + tig * 2;
            float al0 = alpha_s[nloc], al1 = alpha_s[nloc + 1];
            float be0 = beta_s[nloc], be1 = beta_s[nloc + 1];
            size_t r = (size_t)m0 + warpM * 32 + mi * 16 + gid;
            float2 v0 = {acc[mi][ni][0] * al0 + be0, acc[mi][ni][1] * al1 + be1};
            float2 v1 = {acc[mi][ni][2] * al0 + be0, acc[mi][ni][3] * al1 + be1};
            *reinterpret_cast<float2*>(out + r * NDIM + n0 + nloc) = v0;
            *reinterpret_cast<float2*>(out + (r + 8) * NDIM + n0 + nloc) = v1;
        }
    }
}

// ---------------- launch ----------------
extern "C" void kernel_launch(void* const* d_in, const int* in_sizes, int n_in,
                              void* d_out, int out_size) {
    const float* x = (const float*)d_in[0];
    const int* w = (const int*)d_in[1];
    const float* wsc = (const float*)d_in[2];
    const int* wzp = (const int*)d_in[3];
    const float* isc = (const float*)d_in[4];
    const int* izp = (const int*)d_in[5];
    const int* bi = (const int*)d_in[6];
    const float* bsc = (const float*)d_in[7];
    float* out = (float*)d_out;

    cudaFuncSetAttribute(gemm_kernel, cudaFuncAttributeMaxDynamicSharedMemorySize,
                         SMEM_BYTES);

    quant_kernel<<<(int)(((size_t)MDIM * KDIM / 8) / 256), 256>>>(x, isc, izp);
    wconv_kernel<<<(int)(((size_t)NDIM * KDIM / 8) / 256), 256>>>(w, wzp);
    gemm_kernel<<<(MDIM / TILE_M) * (NDIM / TILE_N), THREADS, SMEM_BYTES>>>(
        wsc, isc, bi, bsc, out);
}

// round 6
// speedup vs baseline: 1.3250x; 1.1187x over previous
#include <cuda_runtime.h>
#include <cuda_bf16.h>
#include <cstdint>

#define MDIM 8192
#define KDIM 4096
#define NDIM 4096

#define TILE_M 128
#define TILE_N 256
#define TILE_K 64
#define NK_ITERS (KDIM / TILE_K)   // 64
#define NSTAGES 4
#define THREADS 256

// Tile-major pre-swizzled scratch:
// g_xq: [mt(64)][ks(64)] tiles of 128x64 bf16 (16384 B each), rows 128B, XOR-swizzled
// g_wq: [nt(16)][ks(64)] tiles of 256x64 bf16 (32768 B each)
__device__ __nv_bfloat16 g_xq[(size_t)MDIM * KDIM];
__device__ __nv_bfloat16 g_wq[(size_t)NDIM * KDIM];

#define A_TILE_BYTES 16384
#define B_TILE_BYTES 32768

// ---------------- helpers ----------------
__device__ __forceinline__ uint32_t smem_u32(const void* p) {
    uint32_t a;
    asm("{ .reg .u64 t; cvta.to.shared.u64 t, %1; cvt.u32.u64 %0, t; }" : "=r"(a) : "l"(p));
    return a;
}
__device__ __forceinline__ void ldm_x4(uint32_t* r, uint32_t addr) {
    asm volatile("ldmatrix.sync.aligned.m8n8.x4.shared.b16 {%0,%1,%2,%3}, [%4];"
                 : "=r"(r[0]), "=r"(r[1]), "=r"(r[2]), "=r"(r[3]) : "r"(addr));
}
__device__ __forceinline__ void mma_bf16(float* d, const uint32_t* a, const uint32_t* b) {
    asm volatile(
        "mma.sync.aligned.m16n8k16.row.col.f32.bf16.bf16.f32 "
        "{%0,%1,%2,%3}, {%4,%5,%6,%7}, {%8,%9}, {%0,%1,%2,%3};"
        : "+f"(d[0]), "+f"(d[1]), "+f"(d[2]), "+f"(d[3])
        : "r"(a[0]), "r"(a[1]), "r"(a[2]), "r"(a[3]), "r"(b[0]), "r"(b[1]));
}
__device__ __forceinline__ uint32_t pack_bf16(float a, float b) {
    __nv_bfloat162 t = __floats2bfloat162_rn(a, b);
    return *reinterpret_cast<uint32_t*>(&t);
}
__device__ __forceinline__ void bulk_ld(uint32_t dst, const void* src, uint32_t bytes,
                                        uint32_t mbar) {
    asm volatile(
        "cp.async.bulk.shared::cta.global.mbarrier::complete_tx::bytes [%0], [%1], %2, [%3];"
        :: "r"(dst), "l"(src), "r"(bytes), "r"(mbar) : "memory");
}
#define MBAR_INIT(addr, cnt) \
    asm volatile("mbarrier.init.shared.b64 [%0], %1;" :: "r"(addr), "r"(cnt) : "memory")
#define MBAR_EXPECT_TX(addr, bytes) \
    asm volatile("mbarrier.arrive.expect_tx.shared.b64 _, [%0], %1;" \
                 :: "r"(addr), "r"(bytes) : "memory")
__device__ __forceinline__ void mbar_wait(uint32_t mbar, uint32_t parity) {
    asm volatile(
        "{\n\t"
        ".reg .pred P;\n\t"
        "WAIT_%=:\n\t"
        "mbarrier.try_wait.parity.acquire.cta.shared::cta.b64 P, [%0], %1, 0x989680;\n\t"
        "@P bra DONE_%=;\n\t"
        "bra WAIT_%=;\n\t"
        "DONE_%=:\n\t"
        "}" :: "r"(mbar), "r"(parity) : "memory");
}

// ---------------- quantize x -> bf16(int), tile-major swizzled ----------------
__global__ void __launch_bounds__(256) quant_kernel(const float* __restrict__ x,
                                                    const float* __restrict__ is_p,
                                                    const int* __restrict__ izp_p) {
    size_t base = ((size_t)blockIdx.x * 256 + threadIdx.x) * 8;
    float inv = 1.0f / is_p[0];
    float zp = (float)izp_p[0];
    float4 v0 = *(const float4*)(x + base);
    float4 v1 = *(const float4*)(x + base + 4);
    float q[8];
    q[0] = v0.x; q[1] = v0.y; q[2] = v0.z; q[3] = v0.w;
    q[4] = v1.x; q[5] = v1.y; q[6] = v1.z; q[7] = v1.w;
#pragma unroll
    for (int i = 0; i < 8; i++)
        q[i] = fminf(fmaxf(rintf(q[i] * inv) + zp, -128.f), 127.f) - zp;
    uint4 o;
    o.x = pack_bf16(q[0], q[1]);
    o.y = pack_bf16(q[2], q[3]);
    o.z = pack_bf16(q[4], q[5]);
    o.w = pack_bf16(q[6], q[7]);
    int m = (int)(base >> 12);           // K=4096
    int k = (int)(base & 4095);
    int mt = m >> 7, row = m & 127;
    int ks = k >> 6, u = (k & 63) >> 3;
    size_t dst = (size_t)(mt * 64 + ks) * A_TILE_BYTES +
                 row * 128 + ((u ^ (row & 7)) << 4);
    *reinterpret_cast<uint4*>(reinterpret_cast<char*>(g_xq) + dst) = o;
}

// ---------------- weight int32 -> bf16, tile-major swizzled ----------------
__global__ void __launch_bounds__(256) wconv_kernel(const int* __restrict__ w,
                                                    const int* __restrict__ wzp) {
    size_t base = ((size_t)blockIdx.x * 256 + threadIdx.x) * 8;
    int n = (int)(base >> 12);
    int k = (int)(base & 4095);
    int zp = wzp[n];
    int4 a = *(const int4*)(w + base);
    int4 b = *(const int4*)(w + base + 4);
    uint4 o;
    o.x = pack_bf16((float)(a.x - zp), (float)(a.y - zp));
    o.y = pack_bf16((float)(a.z - zp), (float)(a.w - zp));
    o.z = pack_bf16((float)(b.x - zp), (float)(b.y - zp));
    o.w = pack_bf16((float)(b.z - zp), (float)(b.w - zp));
    int nt = n >> 8, row = n & 255;
    int ks = k >> 6, u = (k & 63) >> 3;
    size_t dst = (size_t)(nt * 64 + ks) * B_TILE_BYTES +
                 row * 128 + ((u ^ (row & 7)) << 4);
    *reinterpret_cast<uint4*>(reinterpret_cast<char*>(g_wq) + dst) = o;
}

// ---------------- HMMA bf16 GEMM: 8 warps, warp 64x64, bulk pipeline ----------------
// smem: [0,32) mbars(4x8B), [128,1152) alpha, [1152,2176) beta, stages @4096
#define S_STAGE (A_TILE_BYTES + B_TILE_BYTES)   // 49152
#define S_BUF 4096
#define SMEM_BYTES (S_BUF + NSTAGES * S_STAGE)  // 200704

__global__ void __launch_bounds__(THREADS, 1)
gemm_kernel(const float* __restrict__ wscale, const float* __restrict__ in_scale,
            const int* __restrict__ bias_int, const float* __restrict__ bias_scale,
            float* __restrict__ out) {
    extern __shared__ __align__(1024) char smem[];
    const uint32_t sbase = smem_u32(smem);
    const int tid = threadIdx.x;
    const int lane = tid & 31;
    const int wid = tid >> 5;
    const int warpM = wid >> 2;       // 2 -> 64 rows each
    const int warpN = wid & 3;        // 4 -> 64 cols each

    // raster: groups of 8 m-tiles x 16 n-tiles (keeps B L2-resident)
    const int tiles_n = NDIM / TILE_N;              // 16
    const int per_group = 8 * tiles_n;              // 128
    int g = blockIdx.x / per_group;
    int r0 = blockIdx.x % per_group;
    int mt = g * 8 + (r0 & 7);
    int nt = r0 >> 3;
    const int m0 = mt * TILE_M;
    const int n0 = nt * TILE_N;

    float* alpha_s = (float*)(smem + 128);
    float* beta_s = (float*)(smem + 1152);
    {
        int n = n0 + tid;
        alpha_s[tid] = in_scale[0] * wscale[n];
        beta_s[tid] = (float)bias_int[n] * bias_scale[n];
    }

    const char* gA = reinterpret_cast<const char*>(g_xq) + (size_t)mt * 64 * A_TILE_BYTES;
    const char* gB = reinterpret_cast<const char*>(g_wq) + (size_t)nt * 64 * B_TILE_BYTES;

    if (tid == 0) {
#pragma unroll
        for (int s = 0; s < NSTAGES; s++) MBAR_INIT(sbase + s * 8, 1);
    }
    __syncthreads();

    // prologue: stages 0..2 in flight
    if (tid == 0) {
#pragma unroll
        for (int s = 0; s < 3; s++) {
            uint32_t mb = sbase + s * 8;
            uint32_t dst = sbase + S_BUF + s * S_STAGE;
            MBAR_EXPECT_TX(mb, S_STAGE);
            bulk_ld(dst, gA + (size_t)s * A_TILE_BYTES, A_TILE_BYTES, mb);
            bulk_ld(dst + A_TILE_BYTES, gB + (size_t)s * B_TILE_BYTES, B_TILE_BYTES, mb);
        }
    }

    float acc[4][8][4];
#pragma unroll
    for (int i = 0; i < 4; i++)
#pragma unroll
        for (int j = 0; j < 8; j++)
#pragma unroll
            for (int q = 0; q < 4; q++) acc[i][j][q] = 0.0f;

    // ldmatrix lane-address components (swizzled rows of 128B)
    const int a_row = lane & 15;
    const int a_kh = (lane >> 4) & 1;
    const int b_noff = (lane & 7) + ((lane & 16) >> 1);
    const int b_kh = (lane >> 3) & 1;

    int rA[4], rB[4];
#pragma unroll
    for (int mi = 0; mi < 4; mi++) rA[mi] = warpM * 64 + mi * 16 + a_row;
#pragma unroll
    for (int np = 0; np < 4; np++) rB[np] = warpN * 64 + np * 16 + b_noff;

#pragma unroll 1
    for (int it = 0; it < NK_ITERS; it++) {
        // prefetch stage it+3 into slot (it+3)&3; slot was released by the
        // __syncthreads() at the end of iter it-1
        if (tid == 0 && it + 3 < NK_ITERS) {
            int s = (it + 3) & (NSTAGES - 1);
            uint32_t mb = sbase + s * 8;
            uint32_t dst = sbase + S_BUF + s * S_STAGE;
            MBAR_EXPECT_TX(mb, S_STAGE);
            bulk_ld(dst, gA + (size_t)(it + 3) * A_TILE_BYTES, A_TILE_BYTES, mb);
            bulk_ld(dst + A_TILE_BYTES, gB + (size_t)(it + 3) * B_TILE_BYTES, B_TILE_BYTES, mb);
        }

        int slot = it & (NSTAGES - 1);
        mbar_wait(sbase + slot * 8, (it >> 2) & 1);

        uint32_t sA = sbase + S_BUF + slot * S_STAGE;
        uint32_t sB = sA + A_TILE_BYTES;

#pragma unroll
        for (int ks = 0; ks < 4; ks++) {   // four k=16 steps
            uint32_t a[4][4], b[4][4];
            int uA = ks * 2 + a_kh;
            int uB = ks * 2 + b_kh;
#pragma unroll
            for (int mi = 0; mi < 4; mi++)
                ldm_x4(a[mi], sA + rA[mi] * 128 + ((uA ^ (rA[mi] & 7)) << 4));
#pragma unroll
            for (int np = 0; np < 4; np++)
                ldm_x4(b[np], sB + rB[np] * 128 + ((uB ^ (rB[np] & 7)) << 4));
#pragma unroll
            for (int mi = 0; mi < 4; mi++)
#pragma unroll
                for (int ni = 0; ni < 8; ni++)
                    mma_bf16(acc[mi][ni], a[mi], &b[ni >> 1][(ni & 1) * 2]);
        }
        __syncthreads();   // release this slot for overwrite
    }

    // epilogue: dequant + bias, direct stores
    const int gid = lane >> 2, tig = lane & 3;
#pragma unroll
    for (int mi = 0; mi < 4; mi++) {
#pragma unroll
        for (int ni = 0; ni < 8; ni++) {
            int nloc = warpN * 64 + ni * 8 + tig * 2;
            float al0 = alpha_s[nloc], al1 = alpha_s[nloc + 1];
            float be0 = beta_s[nloc], be1 = beta_s[nloc + 1];
            size_t r = (size_t)m0 + warpM * 64 + mi * 16 + gid;
            float2 v0 = {acc[mi][ni][0] * al0 + be0, acc[mi][ni][1] * al1 + be1};
            float2 v1 = {acc[mi][ni][2] * al0 + be0, acc[mi][ni][3] * al1 + be1};
            *reinterpret_cast<float2*>(out + r * NDIM + n0 + nloc) = v0;
            *reinterpret_cast<float2*>(out + (r + 8) * NDIM + n0 + nloc) = v1;
        }
    }
}

// ---------------- launch ----------------
extern "C" void kernel_launch(void* const* d_in, const int* in_sizes, int n_in,
                              void* d_out, int out_size) {
    const float* x = (const float*)d_in[0];
    const int* w = (const int*)d_in[1];
    const float* wsc = (const float*)d_in[2];
    const int* wzp = (const int*)d_in[3];
    const float* isc = (const float*)d_in[4];
    const int* izp = (const int*)d_in[5];
    const int* bi = (const int*)d_in[6];
    const float* bsc = (const float*)d_in[7];
    float* out = (float*)d_out;

    cudaFuncSetAttribute(gemm_kernel, cudaFuncAttributeMaxDynamicSharedMemorySize,
                         SMEM_BYTES);

    quant_kernel<<<(int)(((size_t)MDIM * KDIM / 8) / 256), 256>>>(x, isc, izp);
    wconv_kernel<<<(int)(((size_t)NDIM * KDIM / 8) / 256), 256>>>(w, wzp);
    gemm_kernel<<<(MDIM / TILE_M) * (NDIM / TILE_N), THREADS, SMEM_BYTES>>>(
        wsc, isc, bi, bsc, out);
}

// round 7
// speedup vs baseline: 1.3844x; 1.0448x over previous
#include <cuda_runtime.h>
#include <cuda_bf16.h>
#include <cstdint>

#define MDIM 8192
#define KDIM 4096
#define NDIM 4096

#define TILE_M 128
#define TILE_N 256
#define TILE_K 128
#define NK_ITERS (KDIM / TILE_K)   // 32
#define NSTAGES 2
#define THREADS 256

// Tile-major pre-swizzled scratch:
// g_xq: [mt(64)][ks(64)] tiles of 128x64 bf16 (16384 B each), rows 128B, XOR-swizzled
// g_wq: [nt(16)][ks(64)] tiles of 256x64 bf16 (32768 B each)
__device__ __nv_bfloat16 g_xq[(size_t)MDIM * KDIM];
__device__ __nv_bfloat16 g_wq[(size_t)NDIM * KDIM];

#define A_TILE_BYTES 16384
#define B_TILE_BYTES 32768
// per big-iter (TILE_K=128): 2 consecutive k-subtiles each
#define A_STEP (2 * A_TILE_BYTES)   // 32768
#define B_STEP (2 * B_TILE_BYTES)   // 65536

// ---------------- helpers ----------------
__device__ __forceinline__ uint32_t smem_u32(const void* p) {
    uint32_t a;
    asm("{ .reg .u64 t; cvta.to.shared.u64 t, %1; cvt.u32.u64 %0, t; }" : "=r"(a) : "l"(p));
    return a;
}
__device__ __forceinline__ void ldm_x4(uint32_t* r, uint32_t addr) {
    asm volatile("ldmatrix.sync.aligned.m8n8.x4.shared.b16 {%0,%1,%2,%3}, [%4];"
                 : "=r"(r[0]), "=r"(r[1]), "=r"(r[2]), "=r"(r[3]) : "r"(addr));
}
__device__ __forceinline__ void mma_bf16(float* d, const uint32_t* a, const uint32_t* b) {
    asm volatile(
        "mma.sync.aligned.m16n8k16.row.col.f32.bf16.bf16.f32 "
        "{%0,%1,%2,%3}, {%4,%5,%6,%7}, {%8,%9}, {%0,%1,%2,%3};"
        : "+f"(d[0]), "+f"(d[1]), "+f"(d[2]), "+f"(d[3])
        : "r"(a[0]), "r"(a[1]), "r"(a[2]), "r"(a[3]), "r"(b[0]), "r"(b[1]));
}
__device__ __forceinline__ uint32_t pack_bf16(float a, float b) {
    __nv_bfloat162 t = __floats2bfloat162_rn(a, b);
    return *reinterpret_cast<uint32_t*>(&t);
}
__device__ __forceinline__ void bulk_ld(uint32_t dst, const void* src, uint32_t bytes,
                                        uint32_t mbar) {
    asm volatile(
        "cp.async.bulk.shared::cta.global.mbarrier::complete_tx::bytes [%0], [%1], %2, [%3];"
        :: "r"(dst), "l"(src), "r"(bytes), "r"(mbar) : "memory");
}
#define MBAR_INIT(addr, cnt) \
    asm volatile("mbarrier.init.shared.b64 [%0], %1;" :: "r"(addr), "r"(cnt) : "memory")
#define MBAR_EXPECT_TX(addr, bytes) \
    asm volatile("mbarrier.arrive.expect_tx.shared.b64 _, [%0], %1;" \
                 :: "r"(addr), "r"(bytes) : "memory")
__device__ __forceinline__ void mbar_wait(uint32_t mbar, uint32_t parity) {
    asm volatile(
        "{\n\t"
        ".reg .pred P;\n\t"
        "WAIT_%=:\n\t"
        "mbarrier.try_wait.parity.acquire.cta.shared::cta.b64 P, [%0], %1, 0x989680;\n\t"
        "@P bra DONE_%=;\n\t"
        "bra WAIT_%=;\n\t"
        "DONE_%=:\n\t"
        "}" :: "r"(mbar), "r"(parity) : "memory");
}

// ---------------- quantize x -> bf16(int), tile-major swizzled ----------------
__global__ void __launch_bounds__(256) quant_kernel(const float* __restrict__ x,
                                                    const float* __restrict__ is_p,
                                                    const int* __restrict__ izp_p) {
    size_t base = ((size_t)blockIdx.x * 256 + threadIdx.x) * 8;
    float inv = 1.0f / is_p[0];
    float zp = (float)izp_p[0];
    float4 v0 = *(const float4*)(x + base);
    float4 v1 = *(const float4*)(x + base + 4);
    float q[8];
    q[0] = v0.x; q[1] = v0.y; q[2] = v0.z; q[3] = v0.w;
    q[4] = v1.x; q[5] = v1.y; q[6] = v1.z; q[7] = v1.w;
#pragma unroll
    for (int i = 0; i < 8; i++)
        q[i] = fminf(fmaxf(rintf(q[i] * inv) + zp, -128.f), 127.f) - zp;
    uint4 o;
    o.x = pack_bf16(q[0], q[1]);
    o.y = pack_bf16(q[2], q[3]);
    o.z = pack_bf16(q[4], q[5]);
    o.w = pack_bf16(q[6], q[7]);
    int m = (int)(base >> 12);           // K=4096
    int k = (int)(base & 4095);
    int mt = m >> 7, row = m & 127;
    int ks = k >> 6, u = (k & 63) >> 3;
    size_t dst = (size_t)(mt * 64 + ks) * A_TILE_BYTES +
                 row * 128 + ((u ^ (row & 7)) << 4);
    *reinterpret_cast<uint4*>(reinterpret_cast<char*>(g_xq) + dst) = o;
}

// ---------------- weight int32 -> bf16, tile-major swizzled ----------------
__global__ void __launch_bounds__(256) wconv_kernel(const int* __restrict__ w,
                                                    const int* __restrict__ wzp) {
    size_t base = ((size_t)blockIdx.x * 256 + threadIdx.x) * 8;
    int n = (int)(base >> 12);
    int k = (int)(base & 4095);
    int zp = wzp[n];
    int4 a = *(const int4*)(w + base);
    int4 b = *(const int4*)(w + base + 4);
    uint4 o;
    o.x = pack_bf16((float)(a.x - zp), (float)(a.y - zp));
    o.y = pack_bf16((float)(a.z - zp), (float)(a.w - zp));
    o.z = pack_bf16((float)(b.x - zp), (float)(b.y - zp));
    o.w = pack_bf16((float)(b.z - zp), (float)(b.w - zp));
    int nt = n >> 8, row = n & 255;
    int ks = k >> 6, u = (k & 63) >> 3;
    size_t dst = (size_t)(nt * 64 + ks) * B_TILE_BYTES +
                 row * 128 + ((u ^ (row & 7)) << 4);
    *reinterpret_cast<uint4*>(reinterpret_cast<char*>(g_wq) + dst) = o;
}

// ---------------- HMMA bf16 GEMM: 8 warps, warp 64x64, K=128 iters, 2-stage ----------------
// smem: [0,16) mbars(2x8B), [128,1152) alpha, [1152,2176) beta, stages @4096
// stage: A 32KB (2 sub-tiles) + B 64KB (2 sub-tiles) = 96KB
#define S_STAGE (A_STEP + B_STEP)               // 98304
#define S_BUF 4096
#define SMEM_BYTES (S_BUF + NSTAGES * S_STAGE)  // 200704

__global__ void __launch_bounds__(THREADS, 1)
gemm_kernel(const float* __restrict__ wscale, const float* __restrict__ in_scale,
            const int* __restrict__ bias_int, const float* __restrict__ bias_scale,
            float* __restrict__ out) {
    extern __shared__ __align__(1024) char smem[];
    const uint32_t sbase = smem_u32(smem);
    const int tid = threadIdx.x;
    const int lane = tid & 31;
    const int wid = tid >> 5;
    const int warpM = wid >> 2;       // 2 -> 64 rows each
    const int warpN = wid & 3;        // 4 -> 64 cols each

    // raster: groups of 8 m-tiles x 16 n-tiles (keeps B L2-resident)
    const int tiles_n = NDIM / TILE_N;              // 16
    const int per_group = 8 * tiles_n;              // 128
    int g = blockIdx.x / per_group;
    int r0 = blockIdx.x % per_group;
    int mt = g * 8 + (r0 & 7);
    int nt = r0 >> 3;
    const int m0 = mt * TILE_M;
    const int n0 = nt * TILE_N;

    float* alpha_s = (float*)(smem + 128);
    float* beta_s = (float*)(smem + 1152);
    {
        int n = n0 + tid;
        alpha_s[tid] = in_scale[0] * wscale[n];
        beta_s[tid] = (float)bias_int[n] * bias_scale[n];
    }

    const char* gA = reinterpret_cast<const char*>(g_xq) + (size_t)mt * 64 * A_TILE_BYTES;
    const char* gB = reinterpret_cast<const char*>(g_wq) + (size_t)nt * 64 * B_TILE_BYTES;

    if (tid == 0) {
#pragma unroll
        for (int s = 0; s < NSTAGES; s++) MBAR_INIT(sbase + s * 8, 1);
    }
    __syncthreads();

    // prologue: stage 0 in flight
    if (tid == 0) {
        uint32_t mb = sbase;
        uint32_t dst = sbase + S_BUF;
        MBAR_EXPECT_TX(mb, S_STAGE);
        bulk_ld(dst, gA, A_STEP, mb);
        bulk_ld(dst + A_STEP, gB, B_STEP, mb);
    }

    float acc[4][8][4];
#pragma unroll
    for (int i = 0; i < 4; i++)
#pragma unroll
        for (int j = 0; j < 8; j++)
#pragma unroll
            for (int q = 0; q < 4; q++) acc[i][j][q] = 0.0f;

    // ldmatrix lane-address components (swizzled rows of 128B)
    const int a_row = lane & 15;
    const int a_kh = (lane >> 4) & 1;
    const int b_noff = (lane & 7) + ((lane & 16) >> 1);
    const int b_kh = (lane >> 3) & 1;

    int rA[4], rB[4];
#pragma unroll
    for (int mi = 0; mi < 4; mi++) rA[mi] = warpM * 64 + mi * 16 + a_row;
#pragma unroll
    for (int np = 0; np < 4; np++) rB[np] = warpN * 64 + np * 16 + b_noff;

#pragma unroll 1
    for (int it = 0; it < NK_ITERS; it++) {
        // prefetch stage it+1 into the other slot (released by syncthreads at end of it-1)
        if (tid == 0 && it + 1 < NK_ITERS) {
            int s = (it + 1) & 1;
            uint32_t mb = sbase + s * 8;
            uint32_t dst = sbase + S_BUF + s * S_STAGE;
            MBAR_EXPECT_TX(mb, S_STAGE);
            bulk_ld(dst, gA + (size_t)(it + 1) * A_STEP, A_STEP, mb);
            bulk_ld(dst + A_STEP, gB + (size_t)(it + 1) * B_STEP, B_STEP, mb);
        }

        int slot = it & 1;
        mbar_wait(sbase + slot * 8, (it >> 1) & 1);

        uint32_t sA = sbase + S_BUF + slot * S_STAGE;
        uint32_t sB = sA + A_STEP;

#pragma unroll
        for (int ks = 0; ks < 8; ks++) {   // eight k=16 steps
            uint32_t a[4][4], b[4][4];
            uint32_t sAsub = sA + (ks >> 2) * A_TILE_BYTES;
            uint32_t sBsub = sB + (ks >> 2) * B_TILE_BYTES;
            int uA = (ks & 3) * 2 + a_kh;
            int uB = (ks & 3) * 2 + b_kh;
#pragma unroll
            for (int mi = 0; mi < 4; mi++)
                ldm_x4(a[mi], sAsub + rA[mi] * 128 + ((uA ^ (rA[mi] & 7)) << 4));
#pragma unroll
            for (int np = 0; np < 4; np++)
                ldm_x4(b[np], sBsub + rB[np] * 128 + ((uB ^ (rB[np] & 7)) << 4));
#pragma unroll
            for (int mi = 0; mi < 4; mi++)
#pragma unroll
                for (int ni = 0; ni < 8; ni++)
                    mma_bf16(acc[mi][ni], a[mi], &b[ni >> 1][(ni & 1) * 2]);
        }
        __syncthreads();   // release this slot for overwrite
    }

    // epilogue: dequant + bias, direct stores
    const int gid = lane >> 2, tig = lane & 3;
#pragma unroll
    for (int mi = 0; mi < 4; mi++) {
#pragma unroll
        for (int ni = 0; ni < 8; ni++) {
            int nloc = warpN * 64 + ni * 8 + tig * 2;
            float al0 = alpha_s[nloc], al1 = alpha_s[nloc + 1];
            float be0 = beta_s[nloc], be1 = beta_s[nloc + 1];
            size_t r = (size_t)m0 + warpM * 64 + mi * 16 + gid;
            float2 v0 = {acc[mi][ni][0] * al0 + be0, acc[mi][ni][1] * al1 + be1};
            float2 v1 = {acc[mi][ni][2] * al0 + be0, acc[mi][ni][3] * al1 + be1};
            *reinterpret_cast<float2*>(out + r * NDIM + n0 + nloc) = v0;
            *reinterpret_cast<float2*>(out + (r + 8) * NDIM + n0 + nloc) = v1;
        }
    }
}

// ---------------- launch ----------------
extern "C" void kernel_launch(void* const* d_in, const int* in_sizes, int n_in,
                              void* d_out, int out_size) {
    const float* x = (const float*)d_in[0];
    const int* w = (const int*)d_in[1];
    const float* wsc = (const float*)d_in[2];
    const int* wzp = (const int*)d_in[3];
    const float* isc = (const float*)d_in[4];
    const int* izp = (const int*)d_in[5];
    const int* bi = (const int*)d_in[6];
    const float* bsc = (const float*)d_in[7];
    float* out = (float*)d_out;

    cudaFuncSetAttribute(gemm_kernel, cudaFuncAttributeMaxDynamicSharedMemorySize,
                         SMEM_BYTES);

    quant_kernel<<<(int)(((size_t)MDIM * KDIM / 8) / 256), 256>>>(x, isc, izp);
    wconv_kernel<<<(int)(((size_t)NDIM * KDIM / 8) / 256), 256>>>(w, wzp);
    gemm_kernel<<<(MDIM / TILE_M) * (NDIM / TILE_N), THREADS, SMEM_BYTES>>>(
        wsc, isc, bi, bsc, out);
}

// round 8
// speedup vs baseline: 1.4930x; 1.0785x over previous
#include <cuda_runtime.h>
#include <cuda_bf16.h>
#include <cstdint>

#define MDIM 8192
#define KDIM 4096
#define NDIM 4096

#define TILE_M 128
#define TILE_N 256
#define TILE_K 128
#define NK_ITERS (KDIM / TILE_K)   // 32
#define THREADS 256
#define NWARPS (THREADS / 32)

// Tile-major pre-swizzled scratch:
// g_xq: [mt(64)][ks(64)] tiles of 128x64 bf16 (16384 B each), rows 128B, XOR-swizzled
// g_wq: [nt(16)][ks(64)] tiles of 256x64 bf16 (32768 B each)
__device__ __nv_bfloat16 g_xq[(size_t)MDIM * KDIM];
__device__ __nv_bfloat16 g_wq[(size_t)NDIM * KDIM];

#define A_TILE_BYTES 16384
#define B_TILE_BYTES 32768
#define A_STEP (2 * A_TILE_BYTES)   // 32768 per big-iter
#define B_STEP (2 * B_TILE_BYTES)   // 65536 per big-iter

// ---------------- helpers ----------------
__device__ __forceinline__ uint32_t smem_u32(const void* p) {
    uint32_t a;
    asm("{ .reg .u64 t; cvta.to.shared.u64 t, %1; cvt.u32.u64 %0, t; }" : "=r"(a) : "l"(p));
    return a;
}
__device__ __forceinline__ void ldm_x4(uint32_t* r, uint32_t addr) {
    asm volatile("ldmatrix.sync.aligned.m8n8.x4.shared.b16 {%0,%1,%2,%3}, [%4];"
                 : "=r"(r[0]), "=r"(r[1]), "=r"(r[2]), "=r"(r[3]) : "r"(addr));
}
__device__ __forceinline__ void mma_bf16(float* d, const uint32_t* a, const uint32_t* b) {
    asm volatile(
        "mma.sync.aligned.m16n8k16.row.col.f32.bf16.bf16.f32 "
        "{%0,%1,%2,%3}, {%4,%5,%6,%7}, {%8,%9}, {%0,%1,%2,%3};"
        : "+f"(d[0]), "+f"(d[1]), "+f"(d[2]), "+f"(d[3])
        : "r"(a[0]), "r"(a[1]), "r"(a[2]), "r"(a[3]), "r"(b[0]), "r"(b[1]));
}
__device__ __forceinline__ uint32_t pack_bf16(float a, float b) {
    __nv_bfloat162 t = __floats2bfloat162_rn(a, b);
    return *reinterpret_cast<uint32_t*>(&t);
}
__device__ __forceinline__ void bulk_ld(uint32_t dst, const void* src, uint32_t bytes,
                                        uint32_t mbar) {
    asm volatile(
        "cp.async.bulk.shared::cta.global.mbarrier::complete_tx::bytes [%0], [%1], %2, [%3];"
        :: "r"(dst), "l"(src), "r"(bytes), "r"(mbar) : "memory");
}
#define MBAR_INIT(addr, cnt) \
    asm volatile("mbarrier.init.shared.b64 [%0], %1;" :: "r"(addr), "r"(cnt) : "memory")
#define MBAR_EXPECT_TX(addr, bytes) \
    asm volatile("mbarrier.arrive.expect_tx.shared.b64 _, [%0], %1;" \
                 :: "r"(addr), "r"(bytes) : "memory")
#define MBAR_ARRIVE(addr) \
    asm volatile("mbarrier.arrive.release.cta.shared.b64 _, [%0];" :: "r"(addr) : "memory")
__device__ __forceinline__ void mbar_wait(uint32_t mbar, uint32_t parity) {
    asm volatile(
        "{\n\t"
        ".reg .pred P;\n\t"
        "WAIT_%=:\n\t"
        "mbarrier.try_wait.parity.acquire.cta.shared::cta.b64 P, [%0], %1, 0x989680;\n\t"
        "@P bra DONE_%=;\n\t"
        "bra WAIT_%=;\n\t"
        "DONE_%=:\n\t"
        "}" :: "r"(mbar), "r"(parity) : "memory");
}

// ---------------- quantize x -> bf16(int), tile-major swizzled ----------------
__global__ void __launch_bounds__(256) quant_kernel(const float* __restrict__ x,
                                                    const float* __restrict__ is_p,
                                                    const int* __restrict__ izp_p) {
    size_t base = ((size_t)blockIdx.x * 256 + threadIdx.x) * 8;
    float inv = 1.0f / is_p[0];
    float zp = (float)izp_p[0];
    float4 v0 = *(const float4*)(x + base);
    float4 v1 = *(const float4*)(x + base + 4);
    float q[8];
    q[0] = v0.x; q[1] = v0.y; q[2] = v0.z; q[3] = v0.w;
    q[4] = v1.x; q[5] = v1.y; q[6] = v1.z; q[7] = v1.w;
#pragma unroll
    for (int i = 0; i < 8; i++)
        q[i] = fminf(fmaxf(rintf(q[i] * inv) + zp, -128.f), 127.f) - zp;
    uint4 o;
    o.x = pack_bf16(q[0], q[1]);
    o.y = pack_bf16(q[2], q[3]);
    o.z = pack_bf16(q[4], q[5]);
    o.w = pack_bf16(q[6], q[7]);
    int m = (int)(base >> 12);           // K=4096
    int k = (int)(base & 4095);
    int mt = m >> 7, row = m & 127;
    int ks = k >> 6, u = (k & 63) >> 3;
    size_t dst = (size_t)(mt * 64 + ks) * A_TILE_BYTES +
                 row * 128 + ((u ^ (row & 7)) << 4);
    *reinterpret_cast<uint4*>(reinterpret_cast<char*>(g_xq) + dst) = o;
}

// ---------------- weight int32 -> bf16, tile-major swizzled ----------------
__global__ void __launch_bounds__(256) wconv_kernel(const int* __restrict__ w,
                                                    const int* __restrict__ wzp) {
    size_t base = ((size_t)blockIdx.x * 256 + threadIdx.x) * 8;
    int n = (int)(base >> 12);
    int k = (int)(base & 4095);
    int zp = wzp[n];
    int4 a = *(const int4*)(w + base);
    int4 b = *(const int4*)(w + base + 4);
    uint4 o;
    o.x = pack_bf16((float)(a.x - zp), (float)(a.y - zp));
    o.y = pack_bf16((float)(a.z - zp), (float)(a.w - zp));
    o.z = pack_bf16((float)(b.x - zp), (float)(b.y - zp));
    o.w = pack_bf16((float)(b.z - zp), (float)(b.w - zp));
    int nt = n >> 8, row = n & 255;
    int ks = k >> 6, u = (k & 63) >> 3;
    size_t dst = (size_t)(nt * 64 + ks) * B_TILE_BYTES +
                 row * 128 + ((u ^ (row & 7)) << 4);
    *reinterpret_cast<uint4*>(reinterpret_cast<char*>(g_wq) + dst) = o;
}

// ---------------- HMMA bf16 GEMM: producer/consumer mbar pipeline ----------------
// smem: [0,16) full mbars, [16,32) empty mbars, [128,1152) alpha, [1152,2176) beta,
//       stages @4096 (96KB each)
#define S_STAGE (A_STEP + B_STEP)               // 98304
#define S_BUF 4096
#define SMEM_BYTES (S_BUF + 2 * S_STAGE)        // 200704

__global__ void __launch_bounds__(THREADS, 1)
gemm_kernel(const float* __restrict__ wscale, const float* __restrict__ in_scale,
            const int* __restrict__ bias_int, const float* __restrict__ bias_scale,
            float* __restrict__ out) {
    extern __shared__ __align__(1024) char smem[];
    const uint32_t sbase = smem_u32(smem);
    const int tid = threadIdx.x;
    const int lane = tid & 31;
    const int wid = tid >> 5;
    const int warpM = wid >> 2;       // 2 -> 64 rows each
    const int warpN = wid & 3;        // 4 -> 64 cols each

    // raster: groups of 8 m-tiles x 16 n-tiles (keeps B L2-resident)
    const int tiles_n = NDIM / TILE_N;              // 16
    const int per_group = 8 * tiles_n;              // 128
    int g = blockIdx.x / per_group;
    int r0 = blockIdx.x % per_group;
    int mt = g * 8 + (r0 & 7);
    int nt = r0 >> 3;
    const int m0 = mt * TILE_M;
    const int n0 = nt * TILE_N;

    const uint32_t FULL0 = sbase, FULL1 = sbase + 8;
    const uint32_t EMPTY0 = sbase + 16, EMPTY1 = sbase + 24;

    float* alpha_s = (float*)(smem + 128);
    float* beta_s = (float*)(smem + 1152);
    {
        int n = n0 + tid;
        alpha_s[tid] = in_scale[0] * wscale[n];
        beta_s[tid] = (float)bias_int[n] * bias_scale[n];
    }

    const char* gA = reinterpret_cast<const char*>(g_xq) + (size_t)mt * 64 * A_TILE_BYTES;
    const char* gB = reinterpret_cast<const char*>(g_wq) + (size_t)nt * 64 * B_TILE_BYTES;

    if (tid == 0) {
        MBAR_INIT(FULL0, 1);
        MBAR_INIT(FULL1, 1);
        MBAR_INIT(EMPTY0, NWARPS);
        MBAR_INIT(EMPTY1, NWARPS);
    }
    __syncthreads();   // mbar init + alpha/beta visible to all

    // prologue: stage 0 in flight
    if (tid == 0) {
        MBAR_EXPECT_TX(FULL0, S_STAGE);
        bulk_ld(sbase + S_BUF, gA, A_STEP, FULL0);
        bulk_ld(sbase + S_BUF + A_STEP, gB, B_STEP, FULL0);
    }

    float acc[4][8][4];
#pragma unroll
    for (int i = 0; i < 4; i++)
#pragma unroll
        for (int j = 0; j < 8; j++)
#pragma unroll
            for (int q = 0; q < 4; q++) acc[i][j][q] = 0.0f;

    // ldmatrix lane-address components (swizzled rows of 128B)
    const int a_row = lane & 15;
    const int a_kh = (lane >> 4) & 1;
    const int b_noff = (lane & 7) + ((lane & 16) >> 1);
    const int b_kh = (lane >> 3) & 1;

    int rA[4], rB[4];
#pragma unroll
    for (int mi = 0; mi < 4; mi++) rA[mi] = warpM * 64 + mi * 16 + a_row;
#pragma unroll
    for (int np = 0; np < 4; np++) rB[np] = warpN * 64 + np * 16 + b_noff;

#pragma unroll 1
    for (int it = 0; it < NK_ITERS; it++) {
        // producer: issue load for iter it+1 once its slot has been drained
        if (tid == 0 && it + 1 < NK_ITERS) {
            int s = (it + 1) & 1;
            int j = (it + 1) >> 1;               // use-index of this slot
            uint32_t emb = s ? EMPTY1 : EMPTY0;
            uint32_t fmb = s ? FULL1 : FULL0;
            if (j > 0) mbar_wait(emb, (j - 1) & 1);   // consumers of use j-1 done
            MBAR_EXPECT_TX(fmb, S_STAGE);
            uint32_t dst = sbase + S_BUF + s * S_STAGE;
            bulk_ld(dst, gA + (size_t)(it + 1) * A_STEP, A_STEP, fmb);
            bulk_ld(dst + A_STEP, gB + (size_t)(it + 1) * B_STEP, B_STEP, fmb);
        }

        int slot = it & 1;
        mbar_wait(slot ? FULL1 : FULL0, (it >> 1) & 1);

        uint32_t sA = sbase + S_BUF + slot * S_STAGE;
        uint32_t sB = sA + A_STEP;

#pragma unroll
        for (int ks = 0; ks < 8; ks++) {   // eight k=16 steps
            uint32_t a[4][4], b[4][4];
            uint32_t sAsub = sA + (ks >> 2) * A_TILE_BYTES;
            uint32_t sBsub = sB + (ks >> 2) * B_TILE_BYTES;
            int uA = (ks & 3) * 2 + a_kh;
            int uB = (ks & 3) * 2 + b_kh;
#pragma unroll
            for (int mi = 0; mi < 4; mi++)
                ldm_x4(a[mi], sAsub + rA[mi] * 128 + ((uA ^ (rA[mi] & 7)) << 4));
#pragma unroll
            for (int np = 0; np < 4; np++)
                ldm_x4(b[np], sBsub + rB[np] * 128 + ((uB ^ (rB[np] & 7)) << 4));
#pragma unroll
            for (int mi = 0; mi < 4; mi++)
#pragma unroll
                for (int ni = 0; ni < 8; ni++)
                    mma_bf16(acc[mi][ni], a[mi], &b[ni >> 1][(ni & 1) * 2]);
        }

        // this warp is done reading the slot; release it (one arrive per warp)
        if (lane == 0) MBAR_ARRIVE(slot ? EMPTY1 : EMPTY0);
    }

    // epilogue: dequant + bias, direct stores (acc is register-private; alpha/beta
    // were synced before the mainloop)
    const int gid = lane >> 2, tig = lane & 3;
#pragma unroll
    for (int mi = 0; mi < 4; mi++) {
#pragma unroll
        for (int ni = 0; ni < 8; ni++) {
            int nloc = warpN * 64 + ni * 8 + tig * 2;
            float al0 = alpha_s[nloc], al1 = alpha_s[nloc + 1];
            float be0 = beta_s[nloc], be1 = beta_s[nloc + 1];
            size_t r = (size_t)m0 + warpM * 64 + mi * 16 + gid;
            float2 v0 = {acc[mi][ni][0] * al0 + be0, acc[mi][ni][1] * al1 + be1};
            float2 v1 = {acc[mi][ni][2] * al0 + be0, acc[mi][ni][3] * al1 + be1};
            *reinterpret_cast<float2*>(out + r * NDIM + n0 + nloc) = v0;
            *reinterpret_cast<float2*>(out + (r + 8) * NDIM + n0 + nloc) = v1;
        }
    }
}

// ---------------- launch ----------------
extern "C" void kernel_launch(void* const* d_in, const int* in_sizes, int n_in,
                              void* d_out, int out_size) {
    const float* x = (const float*)d_in[0];
    const int* w = (const int*)d_in[1];
    const float* wsc = (const float*)d_in[2];
    const int* wzp = (const int*)d_in[3];
    const float* isc = (const float*)d_in[4];
    const int* izp = (const int*)d_in[5];
    const int* bi = (const int*)d_in[6];
    const float* bsc = (const float*)d_in[7];
    float* out = (float*)d_out;

    cudaFuncSetAttribute(gemm_kernel, cudaFuncAttributeMaxDynamicSharedMemorySize,
                         SMEM_BYTES);

    quant_kernel<<<(int)(((size_t)MDIM * KDIM / 8) / 256), 256>>>(x, isc, izp);
    wconv_kernel<<<(int)(((size_t)NDIM * KDIM / 8) / 256), 256>>>(w, wzp);
    gemm_kernel<<<(MDIM / TILE_M) * (NDIM / TILE_N), THREADS, SMEM_BYTES>>>(
        wsc, isc, bi, bsc, out);
}

// round 9
// speedup vs baseline: 1.4932x; 1.0001x over previous
#include <cuda_runtime.h>
#include <cuda_bf16.h>
#include <cstdint>

#define MDIM 8192
#define KDIM 4096
#define NDIM 4096

#define TILE_M 128
#define TILE_N 256
#define TILE_K 128
#define ITERS_PER_TILE 32
#define NTILES 1024            // 64 m-tiles x 16 n-tiles
#define GRIDX 148
#define THREADS 256
#define NWARPS (THREADS / 32)

// Tile-major pre-swizzled scratch:
// g_xq: [mt(64)][ks(64)] tiles of 128x64 bf16, rows 128B, XOR-swizzled
// g_wq: [nt(16)][ks(64)] tiles of 256x64 bf16
__device__ __nv_bfloat16 g_xq[(size_t)MDIM * KDIM];
__device__ __nv_bfloat16 g_wq[(size_t)NDIM * KDIM];

#define A_TILE_BYTES 16384
#define B_TILE_BYTES 32768
#define A_STEP (2 * A_TILE_BYTES)   // 32768 per big-iter
#define B_STEP (2 * B_TILE_BYTES)   // 65536 per big-iter

// ---------------- helpers ----------------
__device__ __forceinline__ uint32_t smem_u32(const void* p) {
    uint32_t a;
    asm("{ .reg .u64 t; cvta.to.shared.u64 t, %1; cvt.u32.u64 %0, t; }" : "=r"(a) : "l"(p));
    return a;
}
__device__ __forceinline__ void ldm_x4(uint32_t* r, uint32_t addr) {
    asm volatile("ldmatrix.sync.aligned.m8n8.x4.shared.b16 {%0,%1,%2,%3}, [%4];"
                 : "=r"(r[0]), "=r"(r[1]), "=r"(r[2]), "=r"(r[3]) : "r"(addr));
}
__device__ __forceinline__ void mma_bf16(float* d, const uint32_t* a, const uint32_t* b) {
    asm volatile(
        "mma.sync.aligned.m16n8k16.row.col.f32.bf16.bf16.f32 "
        "{%0,%1,%2,%3}, {%4,%5,%6,%7}, {%8,%9}, {%0,%1,%2,%3};"
        : "+f"(d[0]), "+f"(d[1]), "+f"(d[2]), "+f"(d[3])
        : "r"(a[0]), "r"(a[1]), "r"(a[2]), "r"(a[3]), "r"(b[0]), "r"(b[1]));
}
__device__ __forceinline__ uint32_t pack_bf16(float a, float b) {
    __nv_bfloat162 t = __floats2bfloat162_rn(a, b);
    return *reinterpret_cast<uint32_t*>(&t);
}
__device__ __forceinline__ void bulk_ld(uint32_t dst, const void* src, uint32_t bytes,
                                        uint32_t mbar) {
    asm volatile(
        "cp.async.bulk.shared::cta.global.mbarrier::complete_tx::bytes [%0], [%1], %2, [%3];"
        :: "r"(dst), "l"(src), "r"(bytes), "r"(mbar) : "memory");
}
#define MBAR_INIT(addr, cnt) \
    asm volatile("mbarrier.init.shared.b64 [%0], %1;" :: "r"(addr), "r"(cnt) : "memory")
#define MBAR_EXPECT_TX(addr, bytes) \
    asm volatile("mbarrier.arrive.expect_tx.shared.b64 _, [%0], %1;" \
                 :: "r"(addr), "r"(bytes) : "memory")
#define MBAR_ARRIVE(addr) \
    asm volatile("mbarrier.arrive.release.cta.shared.b64 _, [%0];" :: "r"(addr) : "memory")
__device__ __forceinline__ void mbar_wait(uint32_t mbar, uint32_t parity) {
    asm volatile(
        "{\n\t"
        ".reg .pred P;\n\t"
        "WAIT_%=:\n\t"
        "mbarrier.try_wait.parity.acquire.cta.shared::cta.b64 P, [%0], %1, 0x989680;\n\t"
        "@P bra DONE_%=;\n\t"
        "bra WAIT_%=;\n\t"
        "DONE_%=:\n\t"
        "}" :: "r"(mbar), "r"(parity) : "memory");
}

// ---------------- fused prelude: quantize x + convert w, tile-major swizzled ------
// blocks [0, 16384): x quantize (8 floats/thread)
// blocks [16384, 24576): weight convert (8 ints/thread)
__global__ void __launch_bounds__(256) prelude_kernel(const float* __restrict__ x,
                                                      const int* __restrict__ w,
                                                      const float* __restrict__ is_p,
                                                      const int* __restrict__ izp_p,
                                                      const int* __restrict__ wzp) {
    int b = blockIdx.x;
    if (b < 16384) {
        size_t base = ((size_t)b * 256 + threadIdx.x) * 8;
        float inv = 1.0f / is_p[0];
        float zp = (float)izp_p[0];
        float4 v0 = *(const float4*)(x + base);
        float4 v1 = *(const float4*)(x + base + 4);
        float q[8];
        q[0] = v0.x; q[1] = v0.y; q[2] = v0.z; q[3] = v0.w;
        q[4] = v1.x; q[5] = v1.y; q[6] = v1.z; q[7] = v1.w;
#pragma unroll
        for (int i = 0; i < 8; i++)
            q[i] = fminf(fmaxf(rintf(q[i] * inv) + zp, -128.f), 127.f) - zp;
        uint4 o;
        o.x = pack_bf16(q[0], q[1]);
        o.y = pack_bf16(q[2], q[3]);
        o.z = pack_bf16(q[4], q[5]);
        o.w = pack_bf16(q[6], q[7]);
        int m = (int)(base >> 12);
        int k = (int)(base & 4095);
        int mt = m >> 7, row = m & 127;
        int ks = k >> 6, u = (k & 63) >> 3;
        size_t dst = (size_t)(mt * 64 + ks) * A_TILE_BYTES +
                     row * 128 + ((u ^ (row & 7)) << 4);
        *reinterpret_cast<uint4*>(reinterpret_cast<char*>(g_xq) + dst) = o;
    } else {
        size_t base = ((size_t)(b - 16384) * 256 + threadIdx.x) * 8;
        int n = (int)(base >> 12);
        int k = (int)(base & 4095);
        int zp = wzp[n];
        int4 a = *(const int4*)(w + base);
        int4 c = *(const int4*)(w + base + 4);
        uint4 o;
        o.x = pack_bf16((float)(a.x - zp), (float)(a.y - zp));
        o.y = pack_bf16((float)(a.z - zp), (float)(a.w - zp));
        o.z = pack_bf16((float)(c.x - zp), (float)(c.y - zp));
        o.w = pack_bf16((float)(c.z - zp), (float)(c.w - zp));
        int nt = n >> 8, row = n & 255;
        int ks = k >> 6, u = (k & 63) >> 3;
        size_t dst = (size_t)(nt * 64 + ks) * B_TILE_BYTES +
                     row * 128 + ((u ^ (row & 7)) << 4);
        *reinterpret_cast<uint4*>(reinterpret_cast<char*>(g_wq) + dst) = o;
    }
}

// ---------------- persistent HMMA bf16 GEMM ----------------
// smem: [0,16) full mbars, [16,32) empty mbars, stages @4096 (96KB each)
#define S_STAGE (A_STEP + B_STEP)               // 98304
#define S_BUF 4096
#define SMEM_BYTES (S_BUF + 2 * S_STAGE)        // 200704

__device__ __forceinline__ void tile_coords(int t, int& mt, int& nt) {
    int g = t >> 7;          // group of 8 m-tiles x 16 n-tiles
    int r = t & 127;
    mt = g * 8 + (r & 7);
    nt = r >> 3;
}

__global__ void __launch_bounds__(THREADS, 1)
gemm_kernel(const float* __restrict__ wscale, const float* __restrict__ in_scale,
            const int* __restrict__ bias_int, const float* __restrict__ bias_scale,
            float* __restrict__ out) {
    extern __shared__ __align__(1024) char smem[];
    const uint32_t sbase = smem_u32(smem);
    const int tid = threadIdx.x;
    const int lane = tid & 31;
    const int wid = tid >> 5;
    const int warpM = wid >> 2;       // 2 -> 64 rows each
    const int warpN = wid & 3;        // 4 -> 64 cols each

    const uint32_t FULL0 = sbase, FULL1 = sbase + 8;
    const uint32_t EMPTY0 = sbase + 16, EMPTY1 = sbase + 24;

    const char* xbase = reinterpret_cast<const char*>(g_xq);
    const char* wbase = reinterpret_cast<const char*>(g_wq);

    if (tid == 0) {
        MBAR_INIT(FULL0, 1);
        MBAR_INIT(FULL1, 1);
        MBAR_INIT(EMPTY0, NWARPS);
        MBAR_INIT(EMPTY1, NWARPS);
    }
    __syncthreads();

    const float is = in_scale[0];

    int t = blockIdx.x;               // current tile (strided persistent walk)
    int mt, nt;
    tile_coords(t, mt, nt);
    const char* gA = xbase + (size_t)mt * 64 * A_TILE_BYTES;
    const char* gB = wbase + (size_t)nt * 64 * B_TILE_BYTES;

    // prologue: flat position 0 in flight
    if (tid == 0) {
        MBAR_EXPECT_TX(FULL0, S_STAGE);
        bulk_ld(sbase + S_BUF, gA, A_STEP, FULL0);
        bulk_ld(sbase + S_BUF + A_STEP, gB, B_STEP, FULL0);
    }

    float acc[4][8][4];
#pragma unroll
    for (int i = 0; i < 4; i++)
#pragma unroll
        for (int j = 0; j < 8; j++)
#pragma unroll
            for (int q = 0; q < 4; q++) acc[i][j][q] = 0.0f;

    // ldmatrix lane-address components (swizzled rows of 128B)
    const int a_row = lane & 15;
    const int a_kh = (lane >> 4) & 1;
    const int b_noff = (lane & 7) + ((lane & 16) >> 1);
    const int b_kh = (lane >> 3) & 1;

    int rA[4], rB[4];
#pragma unroll
    for (int mi = 0; mi < 4; mi++) rA[mi] = warpM * 64 + mi * 16 + a_row;
#pragma unroll
    for (int np = 0; np < 4; np++) rB[np] = warpN * 64 + np * 16 + b_noff;

    uint32_t git = 0;   // flat global iteration counter (pipeline phase source)

    while (true) {
#pragma unroll 1
        for (int it = 0; it < ITERS_PER_TILE; it++, git++) {
            // producer: issue load for flat position git+1 (next k-iter, possibly
            // the first k-iter of the next tile)
            if (tid == 0) {
                int nit = it + 1;
                int t2 = t;
                const char *bA = gA, *bB = gB;
                if (nit == ITERS_PER_TILE) {
                    nit = 0;
                    t2 = t + GRIDX;
                    if (t2 < NTILES) {
                        int mt2, nt2;
                        tile_coords(t2, mt2, nt2);
                        bA = xbase + (size_t)mt2 * 64 * A_TILE_BYTES;
                        bB = wbase + (size_t)nt2 * 64 * B_TILE_BYTES;
                    }
                }
                if (t2 < NTILES) {
                    uint32_t s = (git + 1) & 1;
                    uint32_t j = (git + 1) >> 1;           // use-index of slot s
                    uint32_t emb = s ? EMPTY1 : EMPTY0;
                    uint32_t fmb = s ? FULL1 : FULL0;
                    if (j > 0) mbar_wait(emb, (j - 1) & 1);
                    MBAR_EXPECT_TX(fmb, S_STAGE);
                    uint32_t dst = sbase + S_BUF + s * S_STAGE;
                    bulk_ld(dst, bA + (size_t)nit * A_STEP, A_STEP, fmb);
                    bulk_ld(dst + A_STEP, bB + (size_t)nit * B_STEP, B_STEP, fmb);
                }
            }

            uint32_t slot = git & 1;
            mbar_wait(slot ? FULL1 : FULL0, (git >> 1) & 1);

            uint32_t sA = sbase + S_BUF + slot * S_STAGE;
            uint32_t sB = sA + A_STEP;

#pragma unroll
            for (int ks = 0; ks < 8; ks++) {   // eight k=16 steps
                uint32_t a[4][4], b[4][4];
                uint32_t sAsub = sA + (ks >> 2) * A_TILE_BYTES;
                uint32_t sBsub = sB + (ks >> 2) * B_TILE_BYTES;
                int uA = (ks & 3) * 2 + a_kh;
                int uB = (ks & 3) * 2 + b_kh;
#pragma unroll
                for (int mi = 0; mi < 4; mi++)
                    ldm_x4(a[mi], sAsub + rA[mi] * 128 + ((uA ^ (rA[mi] & 7)) << 4));
#pragma unroll
                for (int np = 0; np < 4; np++)
                    ldm_x4(b[np], sBsub + rB[np] * 128 + ((uB ^ (rB[np] & 7)) << 4));
#pragma unroll
                for (int mi = 0; mi < 4; mi++)
#pragma unroll
                    for (int ni = 0; ni < 8; ni++)
                        mma_bf16(acc[mi][ni], a[mi], &b[ni >> 1][(ni & 1) * 2]);
            }

            if (lane == 0) MBAR_ARRIVE(slot ? EMPTY1 : EMPTY0);
        }

        // epilogue for tile t (overlaps the next tile's stage-0 load, already in flight)
        {
            const int m0 = mt * TILE_M;
            const int n0 = nt * TILE_N;
            const int gid = lane >> 2, tig = lane & 3;
#pragma unroll
            for (int ni = 0; ni < 8; ni++) {
                int n = n0 + warpN * 64 + ni * 8 + tig * 2;
                float al0 = is * wscale[n];
                float al1 = is * wscale[n + 1];
                float be0 = (float)bias_int[n] * bias_scale[n];
                float be1 = (float)bias_int[n + 1] * bias_scale[n + 1];
#pragma unroll
                for (int mi = 0; mi < 4; mi++) {
                    size_t r = (size_t)m0 + warpM * 64 + mi * 16 + gid;
                    float2 v0 = {acc[mi][ni][0] * al0 + be0, acc[mi][ni][1] * al1 + be1};
                    float2 v1 = {acc[mi][ni][2] * al0 + be0, acc[mi][ni][3] * al1 + be1};
                    *reinterpret_cast<float2*>(out + r * NDIM + n) = v0;
                    *reinterpret_cast<float2*>(out + (r + 8) * NDIM + n) = v1;
                    acc[mi][ni][0] = 0.0f; acc[mi][ni][1] = 0.0f;
                    acc[mi][ni][2] = 0.0f; acc[mi][ni][3] = 0.0f;
                }
            }
        }

        t += GRIDX;
        if (t >= NTILES) break;
        tile_coords(t, mt, nt);
        gA = xbase + (size_t)mt * 64 * A_TILE_BYTES;
        gB = wbase + (size_t)nt * 64 * B_TILE_BYTES;
    }
}

// ---------------- launch ----------------
extern "C" void kernel_launch(void* const* d_in, const int* in_sizes, int n_in,
                              void* d_out, int out_size) {
    const float* x = (const float*)d_in[0];
    const int* w = (const int*)d_in[1];
    const float* wsc = (const float*)d_in[2];
    const int* wzp = (const int*)d_in[3];
    const float* isc = (const float*)d_in[4];
    const int* izp = (const int*)d_in[5];
    const int* bi = (const int*)d_in[6];
    const float* bsc = (const float*)d_in[7];
    float* out = (float*)d_out;

    cudaFuncSetAttribute(gemm_kernel, cudaFuncAttributeMaxDynamicSharedMemorySize,
                         SMEM_BYTES);

    prelude_kernel<<<16384 + 8192, 256>>>(x, w, isc, izp, wzp);
    gemm_kernel<<<GRIDX, THREADS, SMEM_BYTES>>>(wsc, isc, bi, bsc, out);
}